// round 1
// baseline (speedup 1.0000x reference)
#include <cuda_runtime.h>

// Problem constants
#define Bsz  4096
#define Nseq 512
#define Csz  512
#define PHId 128
#define H1d  512
#define H2d  256

// Scratch (no allocations allowed): u (2MB), h1 (8MB), h2 (4MB)
__device__ float g_u [Bsz * PHId];
__device__ float g_h1[Bsz * H1d];
__device__ float g_h2[Bsz * H2d];

// ---------------------------------------------------------------------------
// Stage 1: u[b,:] = sum_j W_phi[x[b,j], :] + Nseq * b_phi
// One warp per batch row; each lane owns 4 phi dims (float4 gathers = LDG.128).
// 8 rows per 256-thread block; x rows staged in smem.
// ---------------------------------------------------------------------------
__global__ void __launch_bounds__(256) phi_kernel(const int* __restrict__ x,
                                                  const float* __restrict__ Wphi,
                                                  const float* __restrict__ bphi)
{
    __shared__ int xs[8 * Nseq];
    const int tid  = threadIdx.x;
    const int warp = tid >> 5;
    const int lane = tid & 31;
    const int rowBase = blockIdx.x * 8;

    const int* xp = x + rowBase * Nseq;
#pragma unroll
    for (int i = 0; i < 16; i++) xs[tid + i * 256] = xp[tid + i * 256];
    __syncthreads();

    const float4* W4 = reinterpret_cast<const float4*>(Wphi);
    const int* xr = xs + warp * Nseq;

    float4 a0 = make_float4(0.f, 0.f, 0.f, 0.f);
    float4 a1 = a0, a2 = a0, a3 = a0;

#pragma unroll 2
    for (int j = 0; j < Nseq; j += 4) {
        const int c0 = xr[j + 0];
        const int c1 = xr[j + 1];
        const int c2 = xr[j + 2];
        const int c3 = xr[j + 3];
        const float4 v0 = W4[c0 * (PHId / 4) + lane];
        const float4 v1 = W4[c1 * (PHId / 4) + lane];
        const float4 v2 = W4[c2 * (PHId / 4) + lane];
        const float4 v3 = W4[c3 * (PHId / 4) + lane];
        a0.x += v0.x; a0.y += v0.y; a0.z += v0.z; a0.w += v0.w;
        a1.x += v1.x; a1.y += v1.y; a1.z += v1.z; a1.w += v1.w;
        a2.x += v2.x; a2.y += v2.y; a2.z += v2.z; a2.w += v2.w;
        a3.x += v3.x; a3.y += v3.y; a3.z += v3.z; a3.w += v3.w;
    }

    const float4 bb = reinterpret_cast<const float4*>(bphi)[lane];
    float4 r;
    r.x = (a0.x + a1.x) + (a2.x + a3.x) + (float)Nseq * bb.x;
    r.y = (a0.y + a1.y) + (a2.y + a3.y) + (float)Nseq * bb.y;
    r.z = (a0.z + a1.z) + (a2.z + a3.z) + (float)Nseq * bb.z;
    r.w = (a0.w + a1.w) + (a2.w + a3.w) + (float)Nseq * bb.w;

    reinterpret_cast<float4*>(g_u)[(rowBase + warp) * (PHId / 4) + lane] = r;
}

// ---------------------------------------------------------------------------
// Register-blocked SGEMM with fused bias (+optional ReLU).
// C[M,N] = act(A[M,K] @ B[K,N] + bias)
// BM=128, BN=64, BK=16; 256 threads, each computes 8x4 outputs.
// M % 128 == 0, N % 64 == 0, K % 16 == 0 (holds for all our shapes).
// ---------------------------------------------------------------------------
template <bool RELU>
__global__ void __launch_bounds__(256) gemm_bias(const float* __restrict__ A,
                                                 const float* __restrict__ Bm,
                                                 const float* __restrict__ bias,
                                                 float* __restrict__ C,
                                                 int M, int N, int K)
{
    constexpr int BM = 128, BN = 64, BK = 16, TM = 8, TN = 4;
    __shared__ float As[BK][BM];
    __shared__ float Bs[BK][BN];

    const int tid = threadIdx.x;
    const int tx  = tid & 15;   // 16 col-groups * TN(4) = 64
    const int ty  = tid >> 4;   // 16 row-groups * TM(8) = 128
    const int rowBase = blockIdx.y * BM;
    const int colBase = blockIdx.x * BN;

    // A-tile load mapping: each thread loads 2 float4 (rows r, r+64)
    const int aRow = tid >> 2;        // 0..63
    const int aK   = (tid & 3) * 4;   // 0,4,8,12
    // B-tile load mapping: each thread loads 1 float4
    const int bK   = tid >> 4;        // 0..15
    const int bCol = (tid & 15) * 4;  // 0..60

    float acc[TM][TN];
#pragma unroll
    for (int i = 0; i < TM; i++)
#pragma unroll
        for (int j = 0; j < TN; j++) acc[i][j] = 0.f;

    for (int k0 = 0; k0 < K; k0 += BK) {
#pragma unroll
        for (int r = 0; r < BM; r += 64) {
            const float4 t = *reinterpret_cast<const float4*>(
                &A[(size_t)(rowBase + aRow + r) * K + k0 + aK]);
            As[aK + 0][aRow + r] = t.x;
            As[aK + 1][aRow + r] = t.y;
            As[aK + 2][aRow + r] = t.z;
            As[aK + 3][aRow + r] = t.w;
        }
        *reinterpret_cast<float4*>(&Bs[bK][bCol]) =
            *reinterpret_cast<const float4*>(&Bm[(size_t)(k0 + bK) * N + colBase + bCol]);
        __syncthreads();

#pragma unroll
        for (int kk = 0; kk < BK; kk++) {
            float a[TM], b[TN];
#pragma unroll
            for (int i = 0; i < TM; i += 4)
                *reinterpret_cast<float4*>(&a[i]) =
                    *reinterpret_cast<const float4*>(&As[kk][ty * TM + i]);
            *reinterpret_cast<float4*>(&b[0]) =
                *reinterpret_cast<const float4*>(&Bs[kk][tx * TN]);
#pragma unroll
            for (int i = 0; i < TM; i++)
#pragma unroll
                for (int j = 0; j < TN; j++)
                    acc[i][j] = fmaf(a[i], b[j], acc[i][j]);
        }
        __syncthreads();
    }

    const float4 bv = *reinterpret_cast<const float4*>(&bias[colBase + tx * TN]);
#pragma unroll
    for (int i = 0; i < TM; i++) {
        const int row = rowBase + ty * TM + i;
        float4 v;
        v.x = acc[i][0] + bv.x;
        v.y = acc[i][1] + bv.y;
        v.z = acc[i][2] + bv.z;
        v.w = acc[i][3] + bv.w;
        if (RELU) {
            v.x = fmaxf(v.x, 0.f);
            v.y = fmaxf(v.y, 0.f);
            v.z = fmaxf(v.z, 0.f);
            v.w = fmaxf(v.w, 0.f);
        }
        *reinterpret_cast<float4*>(&C[(size_t)row * N + colBase + tx * TN]) = v;
    }
}

// ---------------------------------------------------------------------------
// Stage 4: out[b] = h2[b,:] @ W3 + b3.  One warp per row, 8 rows per block.
// ---------------------------------------------------------------------------
__global__ void __launch_bounds__(256) out_kernel(const float* __restrict__ h2,
                                                  const float* __restrict__ W3,
                                                  const float* __restrict__ b3,
                                                  float* __restrict__ out)
{
    __shared__ float w3s[H2d];
    const int tid = threadIdx.x;
    w3s[tid] = W3[tid];
    __syncthreads();

    const int warp = tid >> 5, lane = tid & 31;
    const int row  = blockIdx.x * 8 + warp;
    const float* h = h2 + (size_t)row * H2d;

    float s = 0.f;
#pragma unroll
    for (int i = 0; i < H2d / 32; i++)
        s = fmaf(h[lane + i * 32], w3s[lane + i * 32], s);
#pragma unroll
    for (int o = 16; o; o >>= 1) s += __shfl_xor_sync(0xFFFFFFFFu, s, o);
    if (lane == 0) out[row] = s + b3[0];
}

// ---------------------------------------------------------------------------
extern "C" void kernel_launch(void* const* d_in, const int* in_sizes, int n_in,
                              void* d_out, int out_size)
{
    const int*   x    = (const int*)  d_in[0];
    const float* Wphi = (const float*)d_in[1];
    const float* bphi = (const float*)d_in[2];
    const float* W1   = (const float*)d_in[3];
    const float* b1   = (const float*)d_in[4];
    const float* W2   = (const float*)d_in[5];
    const float* b2   = (const float*)d_in[6];
    const float* W3   = (const float*)d_in[7];
    const float* b3   = (const float*)d_in[8];
    float* out = (float*)d_out;

    float *u_p, *h1_p, *h2_p;
    cudaGetSymbolAddress((void**)&u_p,  g_u);
    cudaGetSymbolAddress((void**)&h1_p, g_h1);
    cudaGetSymbolAddress((void**)&h2_p, g_h2);

    // Stage 1: gather-sum -> u (4096 x 128)
    phi_kernel<<<Bsz / 8, 256>>>(x, Wphi, bphi);

    // Stage 2: h1 = relu(u @ W1 + b1)   (4096x128)@(128x512)
    {
        dim3 grid(H1d / 64, Bsz / 128);
        gemm_bias<true><<<grid, 256>>>(u_p, W1, b1, h1_p, Bsz, H1d, PHId);
    }
    // Stage 3: h2 = relu(h1 @ W2 + b2)  (4096x512)@(512x256)
    {
        dim3 grid(H2d / 64, Bsz / 128);
        gemm_bias<true><<<grid, 256>>>(h1_p, W2, b2, h2_p, Bsz, H2d, H1d);
    }
    // Stage 4: out = h2 @ W3 + b3       (4096x256)@(256x1)
    out_kernel<<<Bsz / 8, 256>>>(h2_p, W3, b3, out);
}

// round 2
// speedup vs baseline: 2.3831x; 2.3831x over previous
#include <cuda_runtime.h>
#include <cuda_fp16.h>
#include <mma.h>

using namespace nvcuda;

#define Bsz  4096
#define Nseq 512
#define Csz  512
#define PHId 128
#define H1d  512
#define H2d  256

// Scratch (__device__ globals; no allocations allowed)
__device__ __half g_hist [Bsz * Csz];    // 4 MB  per-row label histogram (fp16, exact)
__device__ __half g_u    [Bsz * PHId];   // 1 MB  centered u (no 512*b_phi)
__device__ __half g_h1   [Bsz * H1d];    // 4 MB
__device__ float  g_part [4 * Bsz];      // 64 KB partial dots (deterministic reduce)
__device__ __half g_Wphi [Csz * PHId];
__device__ __half g_W1   [PHId * H1d];
__device__ __half g_W2   [H1d * H2d];
__device__ float  g_b1eff[H1d];          // b1 + 512 * (b_phi @ W1), exact fp32

// ---------------------------------------------------------------------------
// Convert weights to fp16; compute b1_eff exactly in fp32.
// ---------------------------------------------------------------------------
__global__ void __launch_bounds__(256) convert_kernel(const float* __restrict__ Wphi,
                                                      const float* __restrict__ W1,
                                                      const float* __restrict__ W2,
                                                      const float* __restrict__ bphi,
                                                      const float* __restrict__ b1)
{
    const int t = blockIdx.x * blockDim.x + threadIdx.x;
    const int stride = gridDim.x * blockDim.x;
    for (int i = t; i < Csz * PHId; i += stride) g_Wphi[i] = __float2half(Wphi[i]);
    for (int i = t; i < PHId * H1d; i += stride) g_W1[i]   = __float2half(W1[i]);
    for (int i = t; i < H1d * H2d;  i += stride) g_W2[i]   = __float2half(W2[i]);
    if (t < H1d) {
        float s = 0.f;
        for (int k = 0; k < PHId; k++) s = fmaf(bphi[k], W1[k * H1d + t], s);
        g_b1eff[t] = b1[t] + (float)Nseq * s;
    }
}

// ---------------------------------------------------------------------------
// Per-row label histogram: 8 rows/block, one warp per row, smem atomics.
// Counts <= 512 are exact in fp16.
// ---------------------------------------------------------------------------
__global__ void __launch_bounds__(256) hist_kernel(const int* __restrict__ x)
{
    __shared__ int hs[8 * Csz];   // 16 KB
    const int tid = threadIdx.x;
#pragma unroll
    for (int i = 0; i < 16; i++) hs[tid + i * 256] = 0;
    __syncthreads();

    const int warp = tid >> 5, lane = tid & 31;
    const int row = blockIdx.x * 8 + warp;
    const int* xr = x + (size_t)row * Nseq;
#pragma unroll 4
    for (int j = lane; j < Nseq; j += 32) atomicAdd(&hs[warp * Csz + xr[j]], 1);
    __syncthreads();

#pragma unroll
    for (int e = tid; e < 8 * Csz; e += 256) {
        const int r = e >> 9, c = e & (Csz - 1);
        g_hist[(size_t)(blockIdx.x * 8 + r) * Csz + c] = __float2half((float)hs[r * Csz + c]);
    }
}

// ---------------------------------------------------------------------------
// fp16 tensor-core GEMM (wmma HMMA, fp32 accum): C = act(A @ B + bias), C fp16.
// BM=128, BN=64, BK=32; 256 threads = 8 warps, each warp 32x32 (2x2 frags).
// ---------------------------------------------------------------------------
template <bool HAS_BIAS, bool RELU>
__global__ void __launch_bounds__(256) hgemm(const __half* __restrict__ A,
                                             const __half* __restrict__ B,
                                             const float* __restrict__ bias,
                                             __half* __restrict__ C,
                                             int M, int N, int K)
{
    constexpr int BM = 128, BN = 64, BK = 32;
    __shared__ __align__(16) union {
        struct { __half A[BM][BK + 8]; __half B[BK][BN + 8]; } in;
        float Cs[BM][BN + 4];
    } sm;

    const int tid  = threadIdx.x;
    const int warp = tid >> 5;
    const int wr   = warp & 3;   // 4 row warp-groups
    const int wc   = warp >> 2;  // 2 col warp-groups
    const int rowBase = blockIdx.y * BM;
    const int colBase = blockIdx.x * BN;

    const int tr = tid >> 2, tc = (tid & 3) << 3;    // A tile map
    const int br = tid >> 3, bc = (tid & 7) << 3;    // B tile map

    wmma::fragment<wmma::accumulator, 16, 16, 16, float> acc[2][2];
#pragma unroll
    for (int i = 0; i < 2; i++)
#pragma unroll
        for (int j = 0; j < 2; j++) wmma::fill_fragment(acc[i][j], 0.f);

    for (int k0 = 0; k0 < K; k0 += BK) {
        const __half* Ag = A + (size_t)rowBase * K + k0;
        *reinterpret_cast<int4*>(&sm.in.A[tr][tc]) =
            *reinterpret_cast<const int4*>(&Ag[(size_t)tr * K + tc]);
        *reinterpret_cast<int4*>(&sm.in.A[tr + 64][tc]) =
            *reinterpret_cast<const int4*>(&Ag[(size_t)(tr + 64) * K + tc]);
        *reinterpret_cast<int4*>(&sm.in.B[br][bc]) =
            *reinterpret_cast<const int4*>(&B[(size_t)(k0 + br) * N + colBase + bc]);
        __syncthreads();

#pragma unroll
        for (int kk = 0; kk < 2; kk++) {
            wmma::fragment<wmma::matrix_a, 16, 16, 16, __half, wmma::row_major> af[2];
            wmma::fragment<wmma::matrix_b, 16, 16, 16, __half, wmma::row_major> bf[2];
#pragma unroll
            for (int i = 0; i < 2; i++)
                wmma::load_matrix_sync(af[i], &sm.in.A[wr * 32 + i * 16][kk * 16], BK + 8);
#pragma unroll
            for (int j = 0; j < 2; j++)
                wmma::load_matrix_sync(bf[j], &sm.in.B[kk * 16][wc * 32 + j * 16], BN + 8);
#pragma unroll
            for (int i = 0; i < 2; i++)
#pragma unroll
                for (int j = 0; j < 2; j++)
                    wmma::mma_sync(acc[i][j], af[i], bf[j], acc[i][j]);
        }
        __syncthreads();
    }

#pragma unroll
    for (int i = 0; i < 2; i++)
#pragma unroll
        for (int j = 0; j < 2; j++)
            wmma::store_matrix_sync(&sm.Cs[wr * 32 + i * 16][wc * 32 + j * 16],
                                    acc[i][j], BN + 4, wmma::mem_row_major);
    __syncthreads();

#pragma unroll 4
    for (int e = tid; e < BM * BN; e += 256) {
        const int r = e >> 6, c = e & 63;
        float v = sm.Cs[r][c];
        if (HAS_BIAS) v += bias[colBase + c];
        if (RELU) v = fmaxf(v, 0.f);
        C[(size_t)(rowBase + r) * N + colBase + c] = __float2half(v);
    }
}

// ---------------------------------------------------------------------------
// Fused stage 3+4: h2tile = relu(h1 @ W2 + b2); part = h2tile @ W3[col slice].
// Same mainloop; epilogue does warp-per-row dot and writes fp32 partials.
// Grid: (H2d/64 = 4 col blocks) x (Bsz/128 row blocks).
// ---------------------------------------------------------------------------
__global__ void __launch_bounds__(256) hgemm_fused(const __half* __restrict__ A,
                                                   const __half* __restrict__ B,
                                                   const float* __restrict__ bias,
                                                   const float* __restrict__ W3,
                                                   int M, int N, int K)
{
    constexpr int BM = 128, BN = 64, BK = 32;
    __shared__ __align__(16) union {
        struct { __half A[BM][BK + 8]; __half B[BK][BN + 8]; } in;
        float Cs[BM][BN + 4];
    } sm;
    __shared__ float w3s[BN];

    const int tid  = threadIdx.x;
    const int warp = tid >> 5;
    const int lane = tid & 31;
    const int wr   = warp & 3;
    const int wc   = warp >> 2;
    const int rowBase = blockIdx.y * BM;
    const int colBase = blockIdx.x * BN;

    if (tid < BN) w3s[tid] = W3[colBase + tid];

    const int tr = tid >> 2, tc = (tid & 3) << 3;
    const int br = tid >> 3, bc = (tid & 7) << 3;

    wmma::fragment<wmma::accumulator, 16, 16, 16, float> acc[2][2];
#pragma unroll
    for (int i = 0; i < 2; i++)
#pragma unroll
        for (int j = 0; j < 2; j++) wmma::fill_fragment(acc[i][j], 0.f);

    for (int k0 = 0; k0 < K; k0 += BK) {
        const __half* Ag = A + (size_t)rowBase * K + k0;
        *reinterpret_cast<int4*>(&sm.in.A[tr][tc]) =
            *reinterpret_cast<const int4*>(&Ag[(size_t)tr * K + tc]);
        *reinterpret_cast<int4*>(&sm.in.A[tr + 64][tc]) =
            *reinterpret_cast<const int4*>(&Ag[(size_t)(tr + 64) * K + tc]);
        *reinterpret_cast<int4*>(&sm.in.B[br][bc]) =
            *reinterpret_cast<const int4*>(&B[(size_t)(k0 + br) * N + colBase + bc]);
        __syncthreads();

#pragma unroll
        for (int kk = 0; kk < 2; kk++) {
            wmma::fragment<wmma::matrix_a, 16, 16, 16, __half, wmma::row_major> af[2];
            wmma::fragment<wmma::matrix_b, 16, 16, 16, __half, wmma::row_major> bf[2];
#pragma unroll
            for (int i = 0; i < 2; i++)
                wmma::load_matrix_sync(af[i], &sm.in.A[wr * 32 + i * 16][kk * 16], BK + 8);
#pragma unroll
            for (int j = 0; j < 2; j++)
                wmma::load_matrix_sync(bf[j], &sm.in.B[kk * 16][wc * 32 + j * 16], BN + 8);
#pragma unroll
            for (int i = 0; i < 2; i++)
#pragma unroll
                for (int j = 0; j < 2; j++)
                    wmma::mma_sync(acc[i][j], af[i], bf[j], acc[i][j]);
        }
        __syncthreads();
    }

#pragma unroll
    for (int i = 0; i < 2; i++)
#pragma unroll
        for (int j = 0; j < 2; j++)
            wmma::store_matrix_sync(&sm.Cs[wr * 32 + i * 16][wc * 32 + j * 16],
                                    acc[i][j], BN + 4, wmma::mem_row_major);
    __syncthreads();

    // warp-per-row dot over 64 cols (bias + relu on the fly), conflict-free smem reads
#pragma unroll
    for (int r = warp; r < BM; r += 8) {
        const float v0 = fmaxf(sm.Cs[r][lane]      + bias[colBase + lane],      0.f);
        const float v1 = fmaxf(sm.Cs[r][lane + 32] + bias[colBase + lane + 32], 0.f);
        float s = fmaf(v0, w3s[lane], v1 * w3s[lane + 32]);
#pragma unroll
        for (int o = 16; o; o >>= 1) s += __shfl_xor_sync(0xFFFFFFFFu, s, o);
        if (lane == 0) g_part[(size_t)blockIdx.x * Bsz + rowBase + r] = s;
    }
}

// ---------------------------------------------------------------------------
// Deterministic final reduce: out[i] = sum of 4 partials + b3.
// ---------------------------------------------------------------------------
__global__ void __launch_bounds__(256) reduce_kernel(const float* __restrict__ b3,
                                                     float* __restrict__ out)
{
    const int i = blockIdx.x * 256 + threadIdx.x;
    out[i] = ((g_part[i] + g_part[Bsz + i]) + (g_part[2 * Bsz + i] + g_part[3 * Bsz + i]))
             + b3[0];
}

// ---------------------------------------------------------------------------
extern "C" void kernel_launch(void* const* d_in, const int* in_sizes, int n_in,
                              void* d_out, int out_size)
{
    const int*   x    = (const int*)  d_in[0];
    const float* Wphi = (const float*)d_in[1];
    const float* bphi = (const float*)d_in[2];
    const float* W1   = (const float*)d_in[3];
    const float* b1   = (const float*)d_in[4];
    const float* W2   = (const float*)d_in[5];
    const float* b2   = (const float*)d_in[6];
    const float* W3   = (const float*)d_in[7];
    const float* b3   = (const float*)d_in[8];
    float* out = (float*)d_out;

    __half *hist_p, *u_p, *h1_p, *Wphi_p, *W1_p, *W2_p;
    float *b1eff_p;
    cudaGetSymbolAddress((void**)&hist_p,  g_hist);
    cudaGetSymbolAddress((void**)&u_p,     g_u);
    cudaGetSymbolAddress((void**)&h1_p,    g_h1);
    cudaGetSymbolAddress((void**)&Wphi_p,  g_Wphi);
    cudaGetSymbolAddress((void**)&W1_p,    g_W1);
    cudaGetSymbolAddress((void**)&W2_p,    g_W2);
    cudaGetSymbolAddress((void**)&b1eff_p, g_b1eff);

    // 0: weight conversion + exact b1_eff
    convert_kernel<<<128, 256>>>(Wphi, W1, W2, bphi, b1);

    // 1: per-row histograms (fp16, exact counts)
    hist_kernel<<<Bsz / 8, 256>>>(x);

    // 2: u_c = hist @ W_phi          (4096x512)@(512x128), no bias/relu
    {
        dim3 grid(PHId / 64, Bsz / 128);
        hgemm<false, false><<<grid, 256>>>(hist_p, Wphi_p, nullptr, u_p, Bsz, PHId, Csz);
    }
    // 3: h1 = relu(u_c @ W1 + b1_eff)  (4096x128)@(128x512)
    {
        dim3 grid(H1d / 64, Bsz / 128);
        hgemm<true, true><<<grid, 256>>>(u_p, W1_p, b1eff_p, h1_p, Bsz, H1d, PHId);
    }
    // 4: fused h2 = relu(h1 @ W2 + b2); partials = h2 @ W3   (4096x512)@(512x256)
    {
        dim3 grid(H2d / 64, Bsz / 128);
        hgemm_fused<<<grid, 256>>>(h1_p, W2_p, b2, W3, Bsz, H2d, H1d);
    }
    // 5: deterministic reduce + b3
    reduce_kernel<<<Bsz / 256, 256>>>(b3, out);
}

// round 3
// speedup vs baseline: 2.9593x; 1.2418x over previous
#include <cuda_runtime.h>
#include <cuda_fp16.h>
#include <mma.h>

using namespace nvcuda;

#define Bsz  4096
#define Nseq 512
#define Csz  512
#define PHId 128
#define H1d  512
#define H2d  256

// Scratch (__device__ globals; no allocations allowed)
__device__ __half g_hist [Bsz * Csz];    // 4 MB  per-row label histogram (fp16, exact)
__device__ __half g_u    [Bsz * PHId];   // 1 MB  centered u (bias folded into b1_eff)
__device__ __half g_h1   [Bsz * H1d];    // 4 MB
__device__ float  g_part [4 * Bsz];      // partial dots (deterministic reduce)
__device__ __half g_Wphi [Csz * PHId];
__device__ __half g_W1   [PHId * H1d];
__device__ __half g_W2   [H1d * H2d];
__device__ float  g_b1eff[H1d];          // b1 + 512 * (b_phi @ W1), exact fp32

// ---------------------------------------------------------------------------
// cp.async helpers (LDGSTS, 16B)
// ---------------------------------------------------------------------------
__device__ __forceinline__ void cp_async16(void* smem, const void* gmem) {
    unsigned s = (unsigned)__cvta_generic_to_shared(smem);
    asm volatile("cp.async.cg.shared.global [%0], [%1], 16;\n" :: "r"(s), "l"(gmem));
}
__device__ __forceinline__ void cp_commit() {
    asm volatile("cp.async.commit_group;\n");
}
template <int NN>
__device__ __forceinline__ void cp_wait() {
    asm volatile("cp.async.wait_group %0;\n" :: "n"(NN));
}

// ---------------------------------------------------------------------------
// Prep kernel: blocks [0,512): per-row histograms (8 rows/block, smem atomics)
//              blocks [512,576): fp32->fp16 weight conversion
//              block  512 also: b1_eff = b1 + 512*(b_phi @ W1) in fp32
// ---------------------------------------------------------------------------
__global__ void __launch_bounds__(256) prep_kernel(const int* __restrict__ x,
                                                   const float* __restrict__ Wphi,
                                                   const float* __restrict__ W1,
                                                   const float* __restrict__ W2,
                                                   const float* __restrict__ bphi,
                                                   const float* __restrict__ b1)
{
    const int tid = threadIdx.x;
    if (blockIdx.x < 512) {
        __shared__ int hs[8 * Csz];   // 16 KB
#pragma unroll
        for (int i = 0; i < 16; i++) hs[tid + i * 256] = 0;
        __syncthreads();

        const int warp = tid >> 5, lane = tid & 31;
        const int row = blockIdx.x * 8 + warp;
        const int* xr = x + (size_t)row * Nseq;
#pragma unroll 4
        for (int j = lane; j < Nseq; j += 32) atomicAdd(&hs[warp * Csz + xr[j]], 1);
        __syncthreads();

#pragma unroll
        for (int e = tid; e < 8 * Csz; e += 256) {
            const int r = e >> 9, c = e & (Csz - 1);
            g_hist[(size_t)(blockIdx.x * 8 + r) * Csz + c] =
                __float2half((float)hs[r * Csz + c]);
        }
    } else {
        const int cb = blockIdx.x - 512;               // 0..63
        const int t = cb * 256 + tid;
        const int stride = 64 * 256;
        for (int i = t; i < Csz * PHId; i += stride) g_Wphi[i] = __float2half(Wphi[i]);
        for (int i = t; i < PHId * H1d; i += stride) g_W1[i]   = __float2half(W1[i]);
        for (int i = t; i < H1d * H2d;  i += stride) g_W2[i]   = __float2half(W2[i]);
        if (cb == 0) {
#pragma unroll
            for (int o = tid; o < H1d; o += 256) {
                float s = 0.f;
                for (int k = 0; k < PHId; k++) s = fmaf(bphi[k], W1[k * H1d + o], s);
                g_b1eff[o] = b1[o] + (float)Nseq * s;
            }
        }
    }
}

// ---------------------------------------------------------------------------
// Pipelined fp16 tensor-core GEMM, fp32 accumulate.
// BM = WR*32, BN = 64, BK = 32, threads = WR*2 warps, warp tile 32x32.
// 3-stage cp.async pipeline. Optional fused W3-dot epilogue (writes g_part).
// ---------------------------------------------------------------------------
template <int WR, bool HAS_BIAS, bool RELU, bool FUSED>
__global__ void __launch_bounds__(WR * 64) gemm_tc(const __half* __restrict__ A,
                                                   const __half* __restrict__ B,
                                                   const float* __restrict__ bias,
                                                   const float* __restrict__ W3,
                                                   __half* __restrict__ C,
                                                   int M, int N, int K)
{
    constexpr int BM = WR * 32, BN = 64, BK = 32, T = WR * 64;
    __shared__ __align__(16) union USM {
        struct { __half A[3][BM][BK + 8]; __half B[3][BK][BN + 8]; } in;
        float Cs[BM][BN + 4];
    } sm;
    __shared__ float w3s[BN];

    const int tid  = threadIdx.x;
    const int warp = tid >> 5;
    const int lane = tid & 31;
    const int wr   = warp % WR;     // row warp-group
    const int wc   = warp / WR;     // col warp-group (0..1)
    const int rowBase = blockIdx.y * BM;
    const int colBase = blockIdx.x * BN;

    if (FUSED && tid < BN) w3s[tid] = W3[colBase + tid];

    // loader maps (all shapes divide evenly)
    const int ar = tid >> 2, ac = (tid & 3) << 3;   // A: BK/8 = 4 chunks/row
    const int br = tid >> 3, bc = (tid & 7) << 3;   // B: BN/8 = 8 chunks/row
    constexpr int RPA = T / 4, RPB = T / 8;

    const __half* Ag = A + (size_t)rowBase * K;
    const __half* Bg = B + colBase;

    auto load_tile = [&](int s, int kt) {
        const __half* Ak = Ag + kt * BK;
#pragma unroll
        for (int r = ar; r < BM; r += RPA)
            cp_async16(&sm.in.A[s][r][ac], Ak + (size_t)r * K + ac);
        const __half* Bk = Bg + (size_t)(kt * BK) * N;
#pragma unroll
        for (int r = br; r < BK; r += RPB)
            cp_async16(&sm.in.B[s][r][bc], Bk + (size_t)r * N + bc);
    };

    wmma::fragment<wmma::accumulator, 16, 16, 16, float> acc[2][2];
#pragma unroll
    for (int i = 0; i < 2; i++)
#pragma unroll
        for (int j = 0; j < 2; j++) wmma::fill_fragment(acc[i][j], 0.f);

    const int KT = K / BK;
    load_tile(0, 0); cp_commit();
    load_tile(1, 1); cp_commit();

    for (int kt = 0; kt < KT; kt++) {
        if (kt + 2 < KT) load_tile((kt + 2) % 3, kt + 2);
        cp_commit();                 // possibly-empty group keeps counting uniform
        cp_wait<2>();
        __syncthreads();

        const int s = kt % 3;
#pragma unroll
        for (int kk = 0; kk < 2; kk++) {
            wmma::fragment<wmma::matrix_a, 16, 16, 16, __half, wmma::row_major> af[2];
            wmma::fragment<wmma::matrix_b, 16, 16, 16, __half, wmma::row_major> bf[2];
#pragma unroll
            for (int i = 0; i < 2; i++)
                wmma::load_matrix_sync(af[i], &sm.in.A[s][wr * 32 + i * 16][kk * 16], BK + 8);
#pragma unroll
            for (int j = 0; j < 2; j++)
                wmma::load_matrix_sync(bf[j], &sm.in.B[s][kk * 16][wc * 32 + j * 16], BN + 8);
#pragma unroll
            for (int i = 0; i < 2; i++)
#pragma unroll
                for (int j = 0; j < 2; j++)
                    wmma::mma_sync(acc[i][j], af[i], bf[j], acc[i][j]);
        }
        __syncthreads();
    }

    // spill accumulators to smem (safe: all cp.async drained, all warps synced)
#pragma unroll
    for (int i = 0; i < 2; i++)
#pragma unroll
        for (int j = 0; j < 2; j++)
            wmma::store_matrix_sync(&sm.Cs[wr * 32 + i * 16][wc * 32 + j * 16],
                                    acc[i][j], BN + 4, wmma::mem_row_major);
    __syncthreads();

    if (!FUSED) {
#pragma unroll 4
        for (int e = tid; e < BM * BN; e += T) {
            const int r = e >> 6, c = e & 63;
            float v = sm.Cs[r][c];
            if (HAS_BIAS) v += bias[colBase + c];
            if (RELU) v = fmaxf(v, 0.f);
            C[(size_t)(rowBase + r) * N + colBase + c] = __float2half(v);
        }
    } else {
        // warp-per-row: relu(bias+acc) dot W3-slice -> fp32 partials
#pragma unroll
        for (int r = warp; r < BM; r += 2 * WR) {
            const float v0 = fmaxf(sm.Cs[r][lane]      + bias[colBase + lane],      0.f);
            const float v1 = fmaxf(sm.Cs[r][lane + 32] + bias[colBase + lane + 32], 0.f);
            float s = fmaf(v0, w3s[lane], v1 * w3s[lane + 32]);
#pragma unroll
            for (int o = 16; o; o >>= 1) s += __shfl_xor_sync(0xFFFFFFFFu, s, o);
            if (lane == 0) g_part[(size_t)blockIdx.x * M + rowBase + r] = s;
        }
    }
}

// ---------------------------------------------------------------------------
// Deterministic final reduce: out[i] = sum of 4 partials + b3.
// ---------------------------------------------------------------------------
__global__ void __launch_bounds__(256) reduce_kernel(const float* __restrict__ b3,
                                                     float* __restrict__ out)
{
    const int i = blockIdx.x * 256 + threadIdx.x;
    out[i] = ((g_part[i] + g_part[Bsz + i]) + (g_part[2 * Bsz + i] + g_part[3 * Bsz + i]))
             + b3[0];
}

// ---------------------------------------------------------------------------
extern "C" void kernel_launch(void* const* d_in, const int* in_sizes, int n_in,
                              void* d_out, int out_size)
{
    const int*   x    = (const int*)  d_in[0];
    const float* Wphi = (const float*)d_in[1];
    const float* bphi = (const float*)d_in[2];
    const float* W1   = (const float*)d_in[3];
    const float* b1   = (const float*)d_in[4];
    const float* W2   = (const float*)d_in[5];
    const float* b2   = (const float*)d_in[6];
    const float* W3   = (const float*)d_in[7];
    const float* b3   = (const float*)d_in[8];
    float* out = (float*)d_out;

    __half *hist_p, *u_p, *h1_p, *Wphi_p, *W1_p, *W2_p;
    float *b1eff_p;
    cudaGetSymbolAddress((void**)&hist_p,  g_hist);
    cudaGetSymbolAddress((void**)&u_p,     g_u);
    cudaGetSymbolAddress((void**)&h1_p,    g_h1);
    cudaGetSymbolAddress((void**)&Wphi_p,  g_Wphi);
    cudaGetSymbolAddress((void**)&W1_p,    g_W1);
    cudaGetSymbolAddress((void**)&W2_p,    g_W2);
    cudaGetSymbolAddress((void**)&b1eff_p, g_b1eff);

    // 0+1: histograms + weight conversion + b1_eff (independent block ranges)
    prep_kernel<<<512 + 64, 256>>>(x, Wphi, W1, W2, bphi, b1);

    // 2: u_c = hist @ W_phi            (4096x512)@(512x128)  BM=64 -> 128 blocks
    {
        dim3 grid(PHId / 64, Bsz / 64);
        gemm_tc<2, false, false, false><<<grid, 128>>>(hist_p, Wphi_p, nullptr, nullptr,
                                                       u_p, Bsz, PHId, Csz);
    }
    // 3: h1 = relu(u_c @ W1 + b1_eff)  (4096x128)@(128x512)  BM=128 -> 256 blocks
    {
        dim3 grid(H1d / 64, Bsz / 128);
        gemm_tc<4, true, true, false><<<grid, 256>>>(u_p, W1_p, b1eff_p, nullptr,
                                                     h1_p, Bsz, H1d, PHId);
    }
    // 4: fused h2 = relu(h1 @ W2 + b2); partials = h2 @ W3    BM=128 -> 128 blocks
    {
        dim3 grid(H2d / 64, Bsz / 128);
        gemm_tc<4, true, true, true><<<grid, 256>>>(h1_p, W2_p, b2, W3,
                                                    nullptr, Bsz, H2d, H1d);
    }
    // 5: deterministic reduce + b3
    reduce_kernel<<<Bsz / 256, 256>>>(b3, out);
}